// round 1
// baseline (speedup 1.0000x reference)
#include <cuda_runtime.h>
#include <math.h>
#include <stdint.h>

// Problem dims (fixed by the reference)
#define HD 1024
#define VD 50257
#define LD 64
#define BD 512

// ---------------------------------------------------------------------------
// Scratch: __device__ globals (allocation-free rule)
// ---------------------------------------------------------------------------
__device__ float g_attnw[BD * LD];           // softmaxed attention weights
__device__ float g_applied[BD * HD];         // attn_weights @ encoder_outputs
__device__ float g_x[BD * HD];               // relu(combine)
__device__ float g_gi[BD * 3 * HD];          // x @ W_ih^T + b_ih
__device__ float g_gh[BD * 3 * HD];          // h0 @ W_hh^T + b_hh
__device__ float g_h1[BD * HD];              // new hidden state

// ---------------------------------------------------------------------------
// K1: scores = [emb|h0] @ attn_W + attn_b ; softmax over L=64
// One block per batch row. 256 threads = 64 cols x 4 k-slices.
// ---------------------------------------------------------------------------
__global__ void k_attn_scores(const float* __restrict__ emb,
                              const float* __restrict__ h0,
                              const float* __restrict__ attn_W,
                              const float* __restrict__ attn_b,
                              float* __restrict__ attnw_scratch,
                              float* __restrict__ attnw_out) {
    const int b   = blockIdx.x;
    const int tid = threadIdx.x;           // 0..255
    const int l   = tid & 63;
    const int s   = tid >> 6;              // 0..3

    const float* arow = emb + (size_t)b * HD;
    const float* hrow = h0  + (size_t)b * HD;

    float acc = 0.f;
    for (int k = s; k < 2 * HD; k += 4) {
        float a = (k < HD) ? arow[k] : hrow[k - HD];
        acc = fmaf(a, attn_W[k * LD + l], acc);
    }

    __shared__ float part[256];
    __shared__ float sc[LD];
    __shared__ float s_max, s_sum;
    part[tid] = acc;
    __syncthreads();
    if (tid < LD) {
        sc[tid] = part[tid] + part[64 + tid] + part[128 + tid] + part[192 + tid]
                  + attn_b[tid];
    }
    __syncthreads();
    if (tid == 0) {
        float m = sc[0];
        #pragma unroll
        for (int i = 1; i < LD; i++) m = fmaxf(m, sc[i]);
        float sum = 0.f;
        #pragma unroll
        for (int i = 0; i < LD; i++) sum += expf(sc[i] - m);
        s_max = m;
        s_sum = sum;
    }
    __syncthreads();
    if (tid < LD) {
        float w = expf(sc[tid] - s_max) / s_sum;
        attnw_scratch[b * LD + tid] = w;
        attnw_out[b * LD + tid]     = w;
    }
}

// ---------------------------------------------------------------------------
// K2: attn_applied[b,:] = attn_weights[b,:] @ encoder_outputs (L x H)
// One block per batch row, 256 threads, 4 h-values per thread.
// ---------------------------------------------------------------------------
__global__ void k_attn_apply(const float* __restrict__ enc,
                             const float* __restrict__ attnw,
                             float* __restrict__ applied) {
    const int b   = blockIdx.x;
    const int tid = threadIdx.x;
    __shared__ float w[LD];
    if (tid < LD) w[tid] = attnw[b * LD + tid];
    __syncthreads();
    for (int h = tid; h < HD; h += 256) {
        float acc = 0.f;
        #pragma unroll 8
        for (int l = 0; l < LD; l++)
            acc = fmaf(w[l], enc[l * HD + h], acc);
        applied[(size_t)b * HD + h] = acc;
    }
}

// ---------------------------------------------------------------------------
// Generic tiled SGEMM: C[M,N] = act( A[M,K] @ B[K,N] + bias )
//   A is (optionally) a concat along K of A1 (M x K1) and A2 (M x (K-K1)).
//   TRANSB=false: B element = Bp[k*ldb + n]   (K x N row-major)
//   TRANSB=true : B element = Bp[n*ldb + k]   (N x K row-major, i.e. A@W^T)
//   ACT: 0 = none, 1 = relu
// Block tile 128x128, BK=16, 256 threads, 8x8 per thread.
// Requires M % 128 == 0, K % 16 == 0. N is guarded.
// ---------------------------------------------------------------------------
template <bool TRANSB, int ACT>
__global__ void __launch_bounds__(256)
sgemm_k(int M, int N, int K,
        const float* __restrict__ A1, int K1, const float* __restrict__ A2,
        const float* __restrict__ Bp, int ldb,
        const float* __restrict__ bias,
        float* __restrict__ C) {
    constexpr int BM = 128, BN = 128, BK = 16, TM = 8, TN = 8;
    __shared__ float As[BK][BM];
    __shared__ float Bs[BK][BN];

    const int tid = threadIdx.x;                 // 0..255
    const int m0  = blockIdx.y * BM;
    const int n0  = blockIdx.x * BN;
    const int K2s = K - K1;

    const int tx = tid % (BN / TN);              // 0..15
    const int ty = tid / (BN / TN);              // 0..15

    float acc[TM][TN];
    #pragma unroll
    for (int i = 0; i < TM; i++)
        #pragma unroll
        for (int j = 0; j < TN; j++) acc[i][j] = 0.f;

    for (int k0 = 0; k0 < K; k0 += BK) {
        // ---- stage A tile (BM x BK), transposed into As[k][m] ----
        #pragma unroll
        for (int i = 0; i < (BM * BK) / 256; i++) {
            int idx = tid + i * 256;
            int ar  = idx / BK;                  // m in tile
            int ac  = idx % BK;                  // k in tile
            int m   = m0 + ar;
            int k   = k0 + ac;
            float v = (k < K1) ? A1[(size_t)m * K1 + k]
                               : A2[(size_t)m * K2s + (k - K1)];
            As[ac][ar] = v;
        }
        // ---- stage B tile (BK x BN) ----
        #pragma unroll
        for (int i = 0; i < (BK * BN) / 256; i++) {
            int idx = tid + i * 256;
            if (!TRANSB) {
                int br = idx / BN;               // k in tile
                int bc = idx % BN;               // n in tile
                int n  = n0 + bc;
                Bs[br][bc] = (n < N) ? Bp[(size_t)(k0 + br) * ldb + n] : 0.f;
            } else {
                int tr = idx / BK;               // n in tile
                int tc = idx % BK;               // k in tile
                int n  = n0 + tr;
                Bs[tc][tr] = (n < N) ? Bp[(size_t)n * ldb + (k0 + tc)] : 0.f;
            }
        }
        __syncthreads();

        #pragma unroll
        for (int kk = 0; kk < BK; kk++) {
            float ra[TM], rb[TN];
            #pragma unroll
            for (int i = 0; i < TM; i++) ra[i] = As[kk][ty * TM + i];
            #pragma unroll
            for (int j = 0; j < TN; j++) rb[j] = Bs[kk][tx * TN + j];
            #pragma unroll
            for (int i = 0; i < TM; i++)
                #pragma unroll
                for (int j = 0; j < TN; j++)
                    acc[i][j] = fmaf(ra[i], rb[j], acc[i][j]);
        }
        __syncthreads();
    }

    // ---- epilogue ----
    #pragma unroll
    for (int i = 0; i < TM; i++) {
        int m = m0 + ty * TM + i;
        #pragma unroll
        for (int j = 0; j < TN; j++) {
            int n = n0 + tx * TN + j;
            if (n < N) {
                float v = acc[i][j] + bias[n];
                if (ACT == 1) v = fmaxf(v, 0.f);
                C[(size_t)m * N + n] = v;
            }
        }
    }
}

// ---------------------------------------------------------------------------
// K5: GRU cell elementwise (PyTorch gate order r,z,n)
// ---------------------------------------------------------------------------
__global__ void k_gru(const float* __restrict__ h0,
                      const float* __restrict__ gi,
                      const float* __restrict__ gh,
                      float* __restrict__ h1_scratch,
                      float* __restrict__ h1_out) {
    int idx = blockIdx.x * blockDim.x + threadIdx.x;
    if (idx >= BD * HD) return;
    int b = idx / HD, j = idx % HD;
    size_t base = (size_t)b * 3 * HD + j;
    float ir = gi[base], iz = gi[base + HD], in = gi[base + 2 * HD];
    float hr = gh[base], hz = gh[base + HD], hn = gh[base + 2 * HD];
    float r = 1.f / (1.f + expf(-(ir + hr)));
    float z = 1.f / (1.f + expf(-(iz + hz)));
    float n = tanhf(in + r * hn);
    float h = (1.f - z) * n + z * h0[idx];
    h1_scratch[idx] = h;
    h1_out[idx]     = h;
}

// ---------------------------------------------------------------------------
// K7: in-place log_softmax over each row of length V
// ---------------------------------------------------------------------------
__global__ void __launch_bounds__(1024)
k_logsoftmax(float* __restrict__ logits) {
    const int b = blockIdx.x;
    float* row  = logits + (size_t)b * VD;
    const int tid = threadIdx.x;
    __shared__ float red[1024];

    float m = -INFINITY;
    for (int v = tid; v < VD; v += 1024) m = fmaxf(m, row[v]);
    red[tid] = m;
    __syncthreads();
    for (int s = 512; s > 0; s >>= 1) {
        if (tid < s) red[tid] = fmaxf(red[tid], red[tid + s]);
        __syncthreads();
    }
    m = red[0];
    __syncthreads();

    float sum = 0.f;
    for (int v = tid; v < VD; v += 1024) sum += expf(row[v] - m);
    red[tid] = sum;
    __syncthreads();
    for (int s = 512; s > 0; s >>= 1) {
        if (tid < s) red[tid] += red[tid + s];
        __syncthreads();
    }
    float lse = m + logf(red[0]);
    __syncthreads();

    for (int v = tid; v < VD; v += 1024) row[v] = row[v] - lse;
}

// ---------------------------------------------------------------------------
// Launch
// ---------------------------------------------------------------------------
extern "C" void kernel_launch(void* const* d_in, const int* in_sizes, int n_in,
                              void* d_out, int out_size) {
    const float* emb    = (const float*)d_in[0];   // (1,B,H)
    const float* h0     = (const float*)d_in[1];   // (1,B,H)
    const float* enc    = (const float*)d_in[2];   // (L,H)
    const float* attn_W = (const float*)d_in[3];   // (2H,L)
    const float* attn_b = (const float*)d_in[4];   // (L,)
    const float* comb_W = (const float*)d_in[5];   // (2H,H)
    const float* comb_b = (const float*)d_in[6];   // (H,)
    const float* W_ih   = (const float*)d_in[7];   // (3H,H)
    const float* W_hh   = (const float*)d_in[8];   // (3H,H)
    const float* b_ih   = (const float*)d_in[9];   // (3H,)
    const float* b_hh   = (const float*)d_in[10];  // (3H,)
    const float* out_W  = (const float*)d_in[11];  // (H,V)
    const float* out_b  = (const float*)d_in[12];  // (V,)

    float* out         = (float*)d_out;
    float* out_logits  = out;                                   // B*V
    float* out_h1      = out + (size_t)BD * VD;                 // B*H
    float* out_attnw   = out_h1 + (size_t)BD * HD;              // B*L

    float *p_attnw, *p_applied, *p_x, *p_gi, *p_gh, *p_h1;
    cudaGetSymbolAddress((void**)&p_attnw,   g_attnw);
    cudaGetSymbolAddress((void**)&p_applied, g_applied);
    cudaGetSymbolAddress((void**)&p_x,       g_x);
    cudaGetSymbolAddress((void**)&p_gi,      g_gi);
    cudaGetSymbolAddress((void**)&p_gh,      g_gh);
    cudaGetSymbolAddress((void**)&p_h1,      g_h1);

    // 1. attention scores + softmax
    k_attn_scores<<<BD, 256>>>(emb, h0, attn_W, attn_b, p_attnw, out_attnw);

    // 2. attn_applied = attn_weights @ encoder_outputs
    k_attn_apply<<<BD, 256>>>(enc, p_attnw, p_applied);

    // 3. x = relu([emb | attn_applied] @ comb_W + comb_b)   (512 x 1024, K=2048)
    {
        dim3 grid(HD / 128, BD / 128);
        sgemm_k<false, 1><<<grid, 256>>>(BD, HD, 2 * HD,
                                         emb, HD, p_applied,
                                         comb_W, HD, comb_b, p_x);
    }

    // 4a. gi = x @ W_ih^T + b_ih   (512 x 3072, K=1024)
    {
        dim3 grid(3 * HD / 128, BD / 128);
        sgemm_k<true, 0><<<grid, 256>>>(BD, 3 * HD, HD,
                                        p_x, HD, nullptr,
                                        W_ih, HD, b_ih, p_gi);
    }
    // 4b. gh = h0 @ W_hh^T + b_hh
    {
        dim3 grid(3 * HD / 128, BD / 128);
        sgemm_k<true, 0><<<grid, 256>>>(BD, 3 * HD, HD,
                                        h0, HD, nullptr,
                                        W_hh, HD, b_hh, p_gh);
    }

    // 5. GRU elementwise -> h1
    k_gru<<<(BD * HD + 255) / 256, 256>>>(h0, p_gi, p_gh, p_h1, out_h1);

    // 6. logits = h1 @ out_W + out_b   (512 x 50257, K=1024) -> d_out in place
    {
        dim3 grid((VD + 127) / 128, BD / 128);
        sgemm_k<false, 0><<<grid, 256>>>(BD, VD, HD,
                                         p_h1, HD, nullptr,
                                         out_W, VD, out_b, out_logits);
    }

    // 7. log_softmax in place
    k_logsoftmax<<<BD, 1024>>>(out_logits);
}

// round 3
// speedup vs baseline: 2.2890x; 2.2890x over previous
#include <cuda_runtime.h>
#include <math.h>
#include <stdint.h>

// Problem dims (fixed by the reference)
#define HD 1024
#define VD 50257
#define LD 64
#define BD 512

// ---------------------------------------------------------------------------
// Scratch: __device__ globals (allocation-free rule)
// ---------------------------------------------------------------------------
__device__ float g_attnw[BD * LD];
__device__ float g_applied[BD * HD];
__device__ float g_x[BD * HD];
__device__ float g_gi[BD * 3 * HD];
__device__ float g_gh[BD * 3 * HD];
__device__ float g_h1[BD * HD];

__device__ __forceinline__ uint32_t f2tf32(float x) {
    uint32_t r;
    asm("cvt.rna.tf32.f32 %0, %1;" : "=r"(r) : "f"(x));
    return r;
}

// ---------------------------------------------------------------------------
// K1: scores = [emb|h0] @ attn_W + attn_b ; softmax over L=64
// ---------------------------------------------------------------------------
__global__ void k_attn_scores(const float* __restrict__ emb,
                              const float* __restrict__ h0,
                              const float* __restrict__ attn_W,
                              const float* __restrict__ attn_b,
                              float* __restrict__ attnw_scratch,
                              float* __restrict__ attnw_out) {
    const int b   = blockIdx.x;
    const int tid = threadIdx.x;           // 0..255
    const int l   = tid & 63;
    const int s   = tid >> 6;              // 0..3

    const float* arow = emb + (size_t)b * HD;
    const float* hrow = h0  + (size_t)b * HD;

    float acc = 0.f;
    for (int k = s; k < 2 * HD; k += 4) {
        float a = (k < HD) ? arow[k] : hrow[k - HD];
        acc = fmaf(a, attn_W[k * LD + l], acc);
    }

    __shared__ float part[256];
    __shared__ float sc[LD];
    __shared__ float s_max, s_sum;
    part[tid] = acc;
    __syncthreads();
    if (tid < LD) {
        sc[tid] = part[tid] + part[64 + tid] + part[128 + tid] + part[192 + tid]
                  + attn_b[tid];
    }
    __syncthreads();
    if (tid == 0) {
        float m = sc[0];
        #pragma unroll
        for (int i = 1; i < LD; i++) m = fmaxf(m, sc[i]);
        float sum = 0.f;
        #pragma unroll
        for (int i = 0; i < LD; i++) sum += expf(sc[i] - m);
        s_max = m;
        s_sum = sum;
    }
    __syncthreads();
    if (tid < LD) {
        float w = expf(sc[tid] - s_max) / s_sum;
        attnw_scratch[b * LD + tid] = w;
        attnw_out[b * LD + tid]     = w;
    }
}

// ---------------------------------------------------------------------------
// K2: attn_applied[b,:] = attn_weights[b,:] @ encoder_outputs (L x H)
// ---------------------------------------------------------------------------
__global__ void k_attn_apply(const float* __restrict__ enc,
                             const float* __restrict__ attnw,
                             float* __restrict__ applied) {
    const int b   = blockIdx.x;
    const int tid = threadIdx.x;
    __shared__ float w[LD];
    if (tid < LD) w[tid] = attnw[b * LD + tid];
    __syncthreads();
    for (int h = tid; h < HD; h += 256) {
        float acc = 0.f;
        #pragma unroll 8
        for (int l = 0; l < LD; l++)
            acc = fmaf(w[l], enc[l * HD + h], acc);
        applied[(size_t)b * HD + h] = acc;
    }
}

// ---------------------------------------------------------------------------
// TF32 tensor-core GEMM: C[M,N] = act( A[M,K] @ op(B) + bias )
//   A optionally concat along K of A1 (M x K1) and A2 (M x (K-K1)).
//   TRANSB=false: B element = Bp[k*ldb + n]  (K x N row-major)
//   TRANSB=true : B element = Bp[n*ldb + k]  (N x K row-major, ldb%4==0, N%128==0)
//   ACT: 0 = none, 1 = relu
// Block tile 128x128x32, 256 threads (8 warps, 2x4), warp tile 64x32,
// mma.sync.m16n8k8.tf32. Requires M%128==0, K%32==0, K1%32==0.
// ---------------------------------------------------------------------------
template <bool TRANSB, int ACT>
__global__ void __launch_bounds__(256, 2)
mma_gemm(int M, int N, int K,
         const float* __restrict__ A1, int K1, const float* __restrict__ A2,
         const float* __restrict__ Bp, int ldb,
         const float* __restrict__ bias,
         float* __restrict__ C) {
    constexpr int BM = 128, BN = 128, BK = 32;
    constexpr int ASTR = BK + 4;     // 36: bank = (4g+t)%32, conflict-free
    constexpr int BSTR_K = BN + 8;   // 136: bank = (8t+g)%32, conflict-free
    constexpr int BSTR_N = BK + 4;   // 36

    __shared__ uint32_t As[BM * ASTR];                 // [m][k]
    __shared__ uint32_t Bs[BM * BSTR_N > BK * BSTR_K ? BM * BSTR_N : BK * BSTR_K];

    const int tid  = threadIdx.x;
    const int m0   = blockIdx.y * BM;
    const int n0   = blockIdx.x * BN;
    const int K2   = K - K1;
    const int lane = tid & 31;
    const int wid  = tid >> 5;
    const int wm   = (wid >> 2) * 64;      // warp row base (0 or 64)
    const int wn   = (wid & 3) * 32;       // warp col base
    const int g    = lane >> 2;            // 0..7
    const int t    = lane & 3;             // 0..3

    float acc[4][4][4];
    #pragma unroll
    for (int i = 0; i < 4; i++)
        #pragma unroll
        for (int j = 0; j < 4; j++)
            #pragma unroll
            for (int c = 0; c < 4; c++) acc[i][j][c] = 0.f;

    for (int k0 = 0; k0 < K; k0 += BK) {
        // ---- stage A (128 x 32), float4 global loads ----
        #pragma unroll
        for (int i = 0; i < 4; i++) {
            int idx = tid + i * 256;       // 0..1023 float4 units
            int m   = idx >> 3;            // 0..127
            int kq  = idx & 7;             // float4 within row
            int k   = k0 + kq * 4;
            const float* src = (k < K1)
                ? (A1 + (size_t)(m0 + m) * K1 + k)
                : (A2 + (size_t)(m0 + m) * K2 + (k - K1));
            float4 v = *(const float4*)src;
            As[m * ASTR + kq * 4 + 0] = f2tf32(v.x);
            As[m * ASTR + kq * 4 + 1] = f2tf32(v.y);
            As[m * ASTR + kq * 4 + 2] = f2tf32(v.z);
            As[m * ASTR + kq * 4 + 3] = f2tf32(v.w);
        }
        // ---- stage B ----
        if (TRANSB) {
            // [n][k] layout; float4 global loads along K
            #pragma unroll
            for (int i = 0; i < 4; i++) {
                int idx = tid + i * 256;   // 0..1023 float4 units
                int n   = idx >> 3;        // 0..127
                int kq  = idx & 7;
                float4 v = *(const float4*)(Bp + (size_t)(n0 + n) * ldb + k0 + kq * 4);
                Bs[n * BSTR_N + kq * 4 + 0] = f2tf32(v.x);
                Bs[n * BSTR_N + kq * 4 + 1] = f2tf32(v.y);
                Bs[n * BSTR_N + kq * 4 + 2] = f2tf32(v.z);
                Bs[n * BSTR_N + kq * 4 + 3] = f2tf32(v.w);
            }
        } else {
            // [k][n] layout; scalar guarded loads (ldb may be odd)
            #pragma unroll
            for (int i = 0; i < 16; i++) {
                int idx = tid + i * 256;   // 0..4095
                int k   = idx >> 7;        // 0..31
                int n   = idx & 127;
                int gn  = n0 + n;
                float v = (gn < N) ? Bp[(size_t)(k0 + k) * ldb + gn] : 0.f;
                Bs[k * BSTR_K + n] = f2tf32(v);
            }
        }
        __syncthreads();

        // ---- compute: 4 k8-steps ----
        #pragma unroll
        for (int kk = 0; kk < 4; kk++) {
            const int kb = kk * 8;
            uint32_t bf[4][2];
            #pragma unroll
            for (int nt = 0; nt < 4; nt++) {
                int n = wn + nt * 8 + g;
                if (TRANSB) {
                    bf[nt][0] = Bs[n * BSTR_N + kb + t];
                    bf[nt][1] = Bs[n * BSTR_N + kb + t + 4];
                } else {
                    bf[nt][0] = Bs[(kb + t) * BSTR_K + n];
                    bf[nt][1] = Bs[(kb + t + 4) * BSTR_K + n];
                }
            }
            #pragma unroll
            for (int mt = 0; mt < 4; mt++) {
                int m = wm + mt * 16 + g;
                uint32_t a0 = As[m * ASTR + kb + t];
                uint32_t a1 = As[(m + 8) * ASTR + kb + t];
                uint32_t a2 = As[m * ASTR + kb + t + 4];
                uint32_t a3 = As[(m + 8) * ASTR + kb + t + 4];
                #pragma unroll
                for (int nt = 0; nt < 4; nt++) {
                    float* c = acc[mt][nt];
                    asm volatile(
                        "mma.sync.aligned.m16n8k8.row.col.f32.tf32.tf32.f32 "
                        "{%0,%1,%2,%3}, {%4,%5,%6,%7}, {%8,%9}, {%0,%1,%2,%3};\n"
                        : "+f"(c[0]), "+f"(c[1]), "+f"(c[2]), "+f"(c[3])
                        : "r"(a0), "r"(a1), "r"(a2), "r"(a3),
                          "r"(bf[nt][0]), "r"(bf[nt][1]));
                }
            }
        }
        __syncthreads();
    }

    // ---- epilogue ----
    #pragma unroll
    for (int mt = 0; mt < 4; mt++) {
        int r0 = m0 + wm + mt * 16 + g;
        #pragma unroll
        for (int nt = 0; nt < 4; nt++) {
            int cn = n0 + wn + nt * 8 + 2 * t;
            float* c = acc[mt][nt];
            if (cn < N) {
                float b0 = bias[cn];
                float v0 = c[0] + b0;
                float v2 = c[2] + b0;
                if (ACT == 1) { v0 = fmaxf(v0, 0.f); v2 = fmaxf(v2, 0.f); }
                C[(size_t)r0 * N + cn]       = v0;
                C[(size_t)(r0 + 8) * N + cn] = v2;
            }
            if (cn + 1 < N) {
                float b1 = bias[cn + 1];
                float v1 = c[1] + b1;
                float v3 = c[3] + b1;
                if (ACT == 1) { v1 = fmaxf(v1, 0.f); v3 = fmaxf(v3, 0.f); }
                C[(size_t)r0 * N + cn + 1]       = v1;
                C[(size_t)(r0 + 8) * N + cn + 1] = v3;
            }
        }
    }
}

// ---------------------------------------------------------------------------
// GRU cell elementwise (PyTorch gate order r,z,n)
// ---------------------------------------------------------------------------
__global__ void k_gru(const float* __restrict__ h0,
                      const float* __restrict__ gi,
                      const float* __restrict__ gh,
                      float* __restrict__ h1_scratch,
                      float* __restrict__ h1_out) {
    int idx = blockIdx.x * blockDim.x + threadIdx.x;
    if (idx >= BD * HD) return;
    int b = idx / HD, j = idx % HD;
    size_t base = (size_t)b * 3 * HD + j;
    float ir = gi[base], iz = gi[base + HD], in = gi[base + 2 * HD];
    float hr = gh[base], hz = gh[base + HD], hn = gh[base + 2 * HD];
    float r = 1.f / (1.f + expf(-(ir + hr)));
    float z = 1.f / (1.f + expf(-(iz + hz)));
    float n = tanhf(in + r * hn);
    float h = (1.f - z) * n + z * h0[idx];
    h1_scratch[idx] = h;
    h1_out[idx]     = h;
}

// ---------------------------------------------------------------------------
// In-place log_softmax, online max+sum (2 passes over the row)
// ---------------------------------------------------------------------------
__global__ void __launch_bounds__(1024)
k_logsoftmax(float* __restrict__ logits) {
    const int b   = blockIdx.x;
    float* row    = logits + (size_t)b * VD;
    const int tid = threadIdx.x;
    __shared__ float sm[1024];
    __shared__ float ss[1024];

    float m = -INFINITY, s = 0.f;
    for (int v = tid; v < VD; v += 1024) {
        float x = row[v];
        if (x > m) {
            s = s * __expf(m - x) + 1.f;
            m = x;
        } else {
            s += __expf(x - m);
        }
    }
    sm[tid] = m;
    ss[tid] = s;
    __syncthreads();
    for (int st = 512; st > 0; st >>= 1) {
        if (tid < st) {
            float m2 = sm[tid + st], s2 = ss[tid + st];
            float M  = fmaxf(sm[tid], m2);
            ss[tid]  = ss[tid] * __expf(sm[tid] - M) + s2 * __expf(m2 - M);
            sm[tid]  = M;
        }
        __syncthreads();
    }
    float lse = sm[0] + logf(ss[0]);
    for (int v = tid; v < VD; v += 1024) row[v] -= lse;
}

// ---------------------------------------------------------------------------
// Launch
// ---------------------------------------------------------------------------
extern "C" void kernel_launch(void* const* d_in, const int* in_sizes, int n_in,
                              void* d_out, int out_size) {
    const float* emb    = (const float*)d_in[0];   // (1,B,H)
    const float* h0     = (const float*)d_in[1];   // (1,B,H)
    const float* enc    = (const float*)d_in[2];   // (L,H)
    const float* attn_W = (const float*)d_in[3];   // (2H,L)
    const float* attn_b = (const float*)d_in[4];   // (L,)
    const float* comb_W = (const float*)d_in[5];   // (2H,H)
    const float* comb_b = (const float*)d_in[6];   // (H,)
    const float* W_ih   = (const float*)d_in[7];   // (3H,H)
    const float* W_hh   = (const float*)d_in[8];   // (3H,H)
    const float* b_ih   = (const float*)d_in[9];   // (3H,)
    const float* b_hh   = (const float*)d_in[10];  // (3H,)
    const float* out_W  = (const float*)d_in[11];  // (H,V)
    const float* out_b  = (const float*)d_in[12];  // (V,)

    float* out        = (float*)d_out;
    float* out_logits = out;                       // B*V
    float* out_h1     = out + (size_t)BD * VD;     // B*H
    float* out_attnw  = out_h1 + (size_t)BD * HD;  // B*L

    float *p_attnw, *p_applied, *p_x, *p_gi, *p_gh, *p_h1;
    cudaGetSymbolAddress((void**)&p_attnw,   g_attnw);
    cudaGetSymbolAddress((void**)&p_applied, g_applied);
    cudaGetSymbolAddress((void**)&p_x,       g_x);
    cudaGetSymbolAddress((void**)&p_gi,      g_gi);
    cudaGetSymbolAddress((void**)&p_gh,      g_gh);
    cudaGetSymbolAddress((void**)&p_h1,      g_h1);

    // 1. attention scores + softmax
    k_attn_scores<<<BD, 256>>>(emb, h0, attn_W, attn_b, p_attnw, out_attnw);

    // 2. attn_applied = attn_weights @ encoder_outputs
    k_attn_apply<<<BD, 256>>>(enc, p_attnw, p_applied);

    // 3. x = relu([emb | attn_applied] @ comb_W + comb_b)
    {
        dim3 grid(HD / 128, BD / 128);
        mma_gemm<false, 1><<<grid, 256>>>(BD, HD, 2 * HD,
                                          emb, HD, p_applied,
                                          comb_W, HD, comb_b, p_x);
    }

    // 4a. gi = x @ W_ih^T + b_ih
    {
        dim3 grid(3 * HD / 128, BD / 128);
        mma_gemm<true, 0><<<grid, 256>>>(BD, 3 * HD, HD,
                                         p_x, HD, nullptr,
                                         W_ih, HD, b_ih, p_gi);
    }
    // 4b. gh = h0 @ W_hh^T + b_hh
    {
        dim3 grid(3 * HD / 128, BD / 128);
        mma_gemm<true, 0><<<grid, 256>>>(BD, 3 * HD, HD,
                                         h0, HD, nullptr,
                                         W_hh, HD, b_hh, p_gh);
    }

    // 5. GRU elementwise -> h1
    k_gru<<<(BD * HD + 255) / 256, 256>>>(h0, p_gi, p_gh, p_h1, out_h1);

    // 6. logits = h1 @ out_W + out_b  -> d_out in place
    {
        dim3 grid((VD + 127) / 128, BD / 128);
        mma_gemm<false, 0><<<grid, 256>>>(BD, VD, HD,
                                          p_h1, HD, nullptr,
                                          out_W, VD, out_b, out_logits);
    }

    // 7. log_softmax in place
    k_logsoftmax<<<BD, 1024>>>(out_logits);
}

// round 4
// speedup vs baseline: 2.2953x; 1.0027x over previous
#include <cuda_runtime.h>
#include <math.h>
#include <stdint.h>

// Problem dims (fixed by the reference)
#define HD 1024
#define VD 50257
#define LD 64
#define BD 512

// ---------------------------------------------------------------------------
// Scratch: __device__ globals (allocation-free rule)
// ---------------------------------------------------------------------------
__device__ float g_attnw[BD * LD];
__device__ float g_applied[BD * HD];
__device__ float g_x[BD * HD];
__device__ float g_gi[BD * 3 * HD];
__device__ float g_gh[BD * 3 * HD];
__device__ float g_h1[BD * HD];

__device__ __forceinline__ uint32_t f2tf32(float x) {
    uint32_t r;
    asm("cvt.rna.tf32.f32 %0, %1;" : "=r"(r) : "f"(x));
    return r;
}

// ---------------------------------------------------------------------------
// K1: scores = [emb|h0] @ attn_W + attn_b ; softmax over L=64
// ---------------------------------------------------------------------------
__global__ void k_attn_scores(const float* __restrict__ emb,
                              const float* __restrict__ h0,
                              const float* __restrict__ attn_W,
                              const float* __restrict__ attn_b,
                              float* __restrict__ attnw_scratch,
                              float* __restrict__ attnw_out) {
    const int b   = blockIdx.x;
    const int tid = threadIdx.x;           // 0..255
    const int l   = tid & 63;
    const int s   = tid >> 6;              // 0..3

    const float* arow = emb + (size_t)b * HD;
    const float* hrow = h0  + (size_t)b * HD;

    float acc = 0.f;
    for (int k = s; k < 2 * HD; k += 4) {
        float a = (k < HD) ? arow[k] : hrow[k - HD];
        acc = fmaf(a, attn_W[k * LD + l], acc);
    }

    __shared__ float part[256];
    __shared__ float sc[LD];
    __shared__ float s_max, s_sum;
    part[tid] = acc;
    __syncthreads();
    if (tid < LD) {
        sc[tid] = part[tid] + part[64 + tid] + part[128 + tid] + part[192 + tid]
                  + attn_b[tid];
    }
    __syncthreads();
    if (tid == 0) {
        float m = sc[0];
        #pragma unroll
        for (int i = 1; i < LD; i++) m = fmaxf(m, sc[i]);
        float sum = 0.f;
        #pragma unroll
        for (int i = 0; i < LD; i++) sum += expf(sc[i] - m);
        s_max = m;
        s_sum = sum;
    }
    __syncthreads();
    if (tid < LD) {
        float w = expf(sc[tid] - s_max) / s_sum;
        attnw_scratch[b * LD + tid] = w;
        attnw_out[b * LD + tid]     = w;
    }
}

// ---------------------------------------------------------------------------
// K2: attn_applied[b,:] = attn_weights[b,:] @ encoder_outputs (L x H)
// ---------------------------------------------------------------------------
__global__ void k_attn_apply(const float* __restrict__ enc,
                             const float* __restrict__ attnw,
                             float* __restrict__ applied) {
    const int b   = blockIdx.x;
    const int tid = threadIdx.x;
    __shared__ float w[LD];
    if (tid < LD) w[tid] = attnw[b * LD + tid];
    __syncthreads();
    for (int h = tid; h < HD; h += 256) {
        float acc = 0.f;
        #pragma unroll 8
        for (int l = 0; l < LD; l++)
            acc = fmaf(w[l], enc[l * HD + h], acc);
        applied[(size_t)b * HD + h] = acc;
    }
}

// ---------------------------------------------------------------------------
// TF32 tensor-core GEMM: C[M,N] = act( A[M,K] @ op(B) + bias )
//   A optionally concat along K of A1 (M x K1) and A2 (M x (K-K1)).
//   TRANSB=false: B element = Bp[k*ldb + n]  (K x N row-major)
//   TRANSB=true : B element = Bp[n*ldb + k]  (N x K row-major, ldb%4==0, N%128==0)
//   ACT: 0 = none, 1 = relu
// Block tile 128x128x32, 256 threads (8 warps, 2x4), warp tile 64x32,
// mma.sync.m16n8k8.tf32. Requires M%128==0, K%32==0, K1%32==0.
// ---------------------------------------------------------------------------
template <bool TRANSB, int ACT>
__global__ void __launch_bounds__(256, 2)
mma_gemm(int M, int N, int K,
         const float* __restrict__ A1, int K1, const float* __restrict__ A2,
         const float* __restrict__ Bp, int ldb,
         const float* __restrict__ bias,
         float* __restrict__ C) {
    constexpr int BM = 128, BN = 128, BK = 32;
    constexpr int ASTR = BK + 4;     // 36: bank = (4g+t)%32, conflict-free
    constexpr int BSTR_K = BN + 8;   // 136: bank = (8t+g)%32, conflict-free
    constexpr int BSTR_N = BK + 4;   // 36

    __shared__ uint32_t As[BM * ASTR];                 // [m][k]
    __shared__ uint32_t Bs[BM * BSTR_N > BK * BSTR_K ? BM * BSTR_N : BK * BSTR_K];

    const int tid  = threadIdx.x;
    const int m0   = blockIdx.y * BM;
    const int n0   = blockIdx.x * BN;
    const int K2   = K - K1;
    const int lane = tid & 31;
    const int wid  = tid >> 5;
    const int wm   = (wid >> 2) * 64;      // warp row base (0 or 64)
    const int wn   = (wid & 3) * 32;       // warp col base
    const int g    = lane >> 2;            // 0..7
    const int t    = lane & 3;             // 0..3

    float acc[4][4][4];
    #pragma unroll
    for (int i = 0; i < 4; i++)
        #pragma unroll
        for (int j = 0; j < 4; j++)
            #pragma unroll
            for (int c = 0; c < 4; c++) acc[i][j][c] = 0.f;

    for (int k0 = 0; k0 < K; k0 += BK) {
        // ---- stage A (128 x 32), float4 global loads ----
        #pragma unroll
        for (int i = 0; i < 4; i++) {
            int idx = tid + i * 256;       // 0..1023 float4 units
            int m   = idx >> 3;            // 0..127
            int kq  = idx & 7;             // float4 within row
            int k   = k0 + kq * 4;
            const float* src = (k < K1)
                ? (A1 + (size_t)(m0 + m) * K1 + k)
                : (A2 + (size_t)(m0 + m) * K2 + (k - K1));
            float4 v = *(const float4*)src;
            As[m * ASTR + kq * 4 + 0] = f2tf32(v.x);
            As[m * ASTR + kq * 4 + 1] = f2tf32(v.y);
            As[m * ASTR + kq * 4 + 2] = f2tf32(v.z);
            As[m * ASTR + kq * 4 + 3] = f2tf32(v.w);
        }
        // ---- stage B ----
        if (TRANSB) {
            // [n][k] layout; float4 global loads along K
            #pragma unroll
            for (int i = 0; i < 4; i++) {
                int idx = tid + i * 256;   // 0..1023 float4 units
                int n   = idx >> 3;        // 0..127
                int kq  = idx & 7;
                float4 v = *(const float4*)(Bp + (size_t)(n0 + n) * ldb + k0 + kq * 4);
                Bs[n * BSTR_N + kq * 4 + 0] = f2tf32(v.x);
                Bs[n * BSTR_N + kq * 4 + 1] = f2tf32(v.y);
                Bs[n * BSTR_N + kq * 4 + 2] = f2tf32(v.z);
                Bs[n * BSTR_N + kq * 4 + 3] = f2tf32(v.w);
            }
        } else {
            // [k][n] layout; scalar guarded loads (ldb may be odd)
            #pragma unroll
            for (int i = 0; i < 16; i++) {
                int idx = tid + i * 256;   // 0..4095
                int k   = idx >> 7;        // 0..31
                int n   = idx & 127;
                int gn  = n0 + n;
                float v = (gn < N) ? Bp[(size_t)(k0 + k) * ldb + gn] : 0.f;
                Bs[k * BSTR_K + n] = f2tf32(v);
            }
        }
        __syncthreads();

        // ---- compute: 4 k8-steps ----
        #pragma unroll
        for (int kk = 0; kk < 4; kk++) {
            const int kb = kk * 8;
            uint32_t bf[4][2];
            #pragma unroll
            for (int nt = 0; nt < 4; nt++) {
                int n = wn + nt * 8 + g;
                if (TRANSB) {
                    bf[nt][0] = Bs[n * BSTR_N + kb + t];
                    bf[nt][1] = Bs[n * BSTR_N + kb + t + 4];
                } else {
                    bf[nt][0] = Bs[(kb + t) * BSTR_K + n];
                    bf[nt][1] = Bs[(kb + t + 4) * BSTR_K + n];
                }
            }
            #pragma unroll
            for (int mt = 0; mt < 4; mt++) {
                int m = wm + mt * 16 + g;
                uint32_t a0 = As[m * ASTR + kb + t];
                uint32_t a1 = As[(m + 8) * ASTR + kb + t];
                uint32_t a2 = As[m * ASTR + kb + t + 4];
                uint32_t a3 = As[(m + 8) * ASTR + kb + t + 4];
                #pragma unroll
                for (int nt = 0; nt < 4; nt++) {
                    float* c = acc[mt][nt];
                    asm volatile(
                        "mma.sync.aligned.m16n8k8.row.col.f32.tf32.tf32.f32 "
                        "{%0,%1,%2,%3}, {%4,%5,%6,%7}, {%8,%9}, {%0,%1,%2,%3};\n"
                        : "+f"(c[0]), "+f"(c[1]), "+f"(c[2]), "+f"(c[3])
                        : "r"(a0), "r"(a1), "r"(a2), "r"(a3),
                          "r"(bf[nt][0]), "r"(bf[nt][1]));
                }
            }
        }
        __syncthreads();
    }

    // ---- epilogue ----
    #pragma unroll
    for (int mt = 0; mt < 4; mt++) {
        int r0 = m0 + wm + mt * 16 + g;
        #pragma unroll
        for (int nt = 0; nt < 4; nt++) {
            int cn = n0 + wn + nt * 8 + 2 * t;
            float* c = acc[mt][nt];
            if (cn < N) {
                float b0 = bias[cn];
                float v0 = c[0] + b0;
                float v2 = c[2] + b0;
                if (ACT == 1) { v0 = fmaxf(v0, 0.f); v2 = fmaxf(v2, 0.f); }
                C[(size_t)r0 * N + cn]       = v0;
                C[(size_t)(r0 + 8) * N + cn] = v2;
            }
            if (cn + 1 < N) {
                float b1 = bias[cn + 1];
                float v1 = c[1] + b1;
                float v3 = c[3] + b1;
                if (ACT == 1) { v1 = fmaxf(v1, 0.f); v3 = fmaxf(v3, 0.f); }
                C[(size_t)r0 * N + cn + 1]       = v1;
                C[(size_t)(r0 + 8) * N + cn + 1] = v3;
            }
        }
    }
}

// ---------------------------------------------------------------------------
// GRU cell elementwise (PyTorch gate order r,z,n)
// ---------------------------------------------------------------------------
__global__ void k_gru(const float* __restrict__ h0,
                      const float* __restrict__ gi,
                      const float* __restrict__ gh,
                      float* __restrict__ h1_scratch,
                      float* __restrict__ h1_out) {
    int idx = blockIdx.x * blockDim.x + threadIdx.x;
    if (idx >= BD * HD) return;
    int b = idx / HD, j = idx % HD;
    size_t base = (size_t)b * 3 * HD + j;
    float ir = gi[base], iz = gi[base + HD], in = gi[base + 2 * HD];
    float hr = gh[base], hz = gh[base + HD], hn = gh[base + 2 * HD];
    float r = 1.f / (1.f + expf(-(ir + hr)));
    float z = 1.f / (1.f + expf(-(iz + hz)));
    float n = tanhf(in + r * hn);
    float h = (1.f - z) * n + z * h0[idx];
    h1_scratch[idx] = h;
    h1_out[idx]     = h;
}

// ---------------------------------------------------------------------------
// In-place log_softmax, online max+sum (2 passes over the row)
// ---------------------------------------------------------------------------
__global__ void __launch_bounds__(1024)
k_logsoftmax(float* __restrict__ logits) {
    const int b   = blockIdx.x;
    float* row    = logits + (size_t)b * VD;
    const int tid = threadIdx.x;
    __shared__ float sm[1024];
    __shared__ float ss[1024];

    float m = -INFINITY, s = 0.f;
    for (int v = tid; v < VD; v += 1024) {
        float x = row[v];
        if (x > m) {
            s = s * __expf(m - x) + 1.f;
            m = x;
        } else {
            s += __expf(x - m);
        }
    }
    sm[tid] = m;
    ss[tid] = s;
    __syncthreads();
    for (int st = 512; st > 0; st >>= 1) {
        if (tid < st) {
            float m2 = sm[tid + st], s2 = ss[tid + st];
            float M  = fmaxf(sm[tid], m2);
            ss[tid]  = ss[tid] * __expf(sm[tid] - M) + s2 * __expf(m2 - M);
            sm[tid]  = M;
        }
        __syncthreads();
    }
    float lse = sm[0] + logf(ss[0]);
    for (int v = tid; v < VD; v += 1024) row[v] -= lse;
}

// ---------------------------------------------------------------------------
// Launch
// ---------------------------------------------------------------------------
extern "C" void kernel_launch(void* const* d_in, const int* in_sizes, int n_in,
                              void* d_out, int out_size) {
    const float* emb    = (const float*)d_in[0];   // (1,B,H)
    const float* h0     = (const float*)d_in[1];   // (1,B,H)
    const float* enc    = (const float*)d_in[2];   // (L,H)
    const float* attn_W = (const float*)d_in[3];   // (2H,L)
    const float* attn_b = (const float*)d_in[4];   // (L,)
    const float* comb_W = (const float*)d_in[5];   // (2H,H)
    const float* comb_b = (const float*)d_in[6];   // (H,)
    const float* W_ih   = (const float*)d_in[7];   // (3H,H)
    const float* W_hh   = (const float*)d_in[8];   // (3H,H)
    const float* b_ih   = (const float*)d_in[9];   // (3H,)
    const float* b_hh   = (const float*)d_in[10];  // (3H,)
    const float* out_W  = (const float*)d_in[11];  // (H,V)
    const float* out_b  = (const float*)d_in[12];  // (V,)

    float* out        = (float*)d_out;
    float* out_logits = out;                       // B*V
    float* out_h1     = out + (size_t)BD * VD;     // B*H
    float* out_attnw  = out_h1 + (size_t)BD * HD;  // B*L

    float *p_attnw, *p_applied, *p_x, *p_gi, *p_gh, *p_h1;
    cudaGetSymbolAddress((void**)&p_attnw,   g_attnw);
    cudaGetSymbolAddress((void**)&p_applied, g_applied);
    cudaGetSymbolAddress((void**)&p_x,       g_x);
    cudaGetSymbolAddress((void**)&p_gi,      g_gi);
    cudaGetSymbolAddress((void**)&p_gh,      g_gh);
    cudaGetSymbolAddress((void**)&p_h1,      g_h1);

    // 1. attention scores + softmax
    k_attn_scores<<<BD, 256>>>(emb, h0, attn_W, attn_b, p_attnw, out_attnw);

    // 2. attn_applied = attn_weights @ encoder_outputs
    k_attn_apply<<<BD, 256>>>(enc, p_attnw, p_applied);

    // 3. x = relu([emb | attn_applied] @ comb_W + comb_b)
    {
        dim3 grid(HD / 128, BD / 128);
        mma_gemm<false, 1><<<grid, 256>>>(BD, HD, 2 * HD,
                                          emb, HD, p_applied,
                                          comb_W, HD, comb_b, p_x);
    }

    // 4a. gi = x @ W_ih^T + b_ih
    {
        dim3 grid(3 * HD / 128, BD / 128);
        mma_gemm<true, 0><<<grid, 256>>>(BD, 3 * HD, HD,
                                         p_x, HD, nullptr,
                                         W_ih, HD, b_ih, p_gi);
    }
    // 4b. gh = h0 @ W_hh^T + b_hh
    {
        dim3 grid(3 * HD / 128, BD / 128);
        mma_gemm<true, 0><<<grid, 256>>>(BD, 3 * HD, HD,
                                         h0, HD, nullptr,
                                         W_hh, HD, b_hh, p_gh);
    }

    // 5. GRU elementwise -> h1
    k_gru<<<(BD * HD + 255) / 256, 256>>>(h0, p_gi, p_gh, p_h1, out_h1);

    // 6. logits = h1 @ out_W + out_b  -> d_out in place
    {
        dim3 grid((VD + 127) / 128, BD / 128);
        mma_gemm<false, 0><<<grid, 256>>>(BD, VD, HD,
                                          p_h1, HD, nullptr,
                                          out_W, VD, out_b, out_logits);
    }

    // 7. log_softmax in place
    k_logsoftmax<<<BD, 1024>>>(out_logits);
}